// round 4
// baseline (speedup 1.0000x reference)
#include <cuda_runtime.h>

#define H      256
#define OUTN   200
#define DIN    20
#define TSTEPS 150
#define BB     14
#define P      7          // BB/2 packed row-pairs
#define BETA   0.9f
#define THR    1.0f

// Transposed weights scratch: Wt[i*H + j] = W[j][i]; Wout padded to 256 cols.
// Offsets (floats): W1t 0..5120, W2t, W3t, W4t, WOt (+2048 overrun pad for prefetch)
#define OFF_W1 0
#define OFF_W2 5120
#define OFF_W3 (5120 + 65536)
#define OFF_W4 (5120 + 2*65536)
#define OFF_WO (5120 + 3*65536)
#define WT_TOTAL (5120 + 4*65536)
__device__ float g_Wt[WT_TOTAL + 2048];

typedef unsigned long long u64;

__device__ __forceinline__ u64 ffma2(u64 a, u64 b, u64 c) {
    u64 d;
    asm("fma.rn.f32x2 %0, %1, %2, %3;" : "=l"(d) : "l"(a), "l"(b), "l"(c));
    return d;
}
__device__ __forceinline__ u64 pack2(float w) {
    u64 d;
    asm("mov.b64 %0, {%1, %1};" : "=l"(d) : "f"(w));
    return d;
}
__device__ __forceinline__ void unpack2(u64 a, float& x, float& y) {
    asm("mov.b64 {%0, %1}, %2;" : "=f"(x), "=f"(y) : "l"(a));
}

// GEMM slice for one output neuron j over K inputs, BB=14 batch rows packed
// as P=7 f32x2 pairs. Spikes/inputs in SMEM as float2 pairs, [p*H + i].
// Uniform-address LDS.128 -> broadcast (conflict-free). Weights: coalesced LDG
// with distance-2 (8 rows) software prefetch; overruns land in the next weight
// region / the 2048-float tail pad (values discarded).
template<int K>
__device__ __forceinline__ void gemm_layer(const float* __restrict__ Wt,
                                           const float2* __restrict__ sb,
                                           int j, u64* acc2) {
#pragma unroll
    for (int p = 0; p < P; p++) acc2[p] = 0ull;
    float c0 = Wt[0*H + j], c1 = Wt[1*H + j], c2 = Wt[2*H + j], c3 = Wt[3*H + j];
    float n0 = Wt[4*H + j], n1 = Wt[5*H + j], n2 = Wt[6*H + j], n3 = Wt[7*H + j];
#pragma unroll 2
    for (int i = 0; i < K; i += 4) {
        float f0 = Wt[(i+8)*H + j];
        float f1 = Wt[(i+9)*H + j];
        float f2 = Wt[(i+10)*H + j];
        float f3 = Wt[(i+11)*H + j];
        u64 W0 = pack2(c0), W1 = pack2(c1), W2 = pack2(c2), W3 = pack2(c3);
#pragma unroll
        for (int p = 0; p < P; p++) {
            const ulonglong2* s = reinterpret_cast<const ulonglong2*>(sb + p*H + i);
            ulonglong2 ab = s[0];   // pairs (i), (i+1) — already f32x2-packed
            ulonglong2 cd = s[1];   // pairs (i+2), (i+3)
            acc2[p] = ffma2(W0, ab.x, acc2[p]);
            acc2[p] = ffma2(W1, ab.y, acc2[p]);
            acc2[p] = ffma2(W2, cd.x, acc2[p]);
            acc2[p] = ffma2(W3, cd.y, acc2[p]);
        }
        c0 = n0; c1 = n1; c2 = n2; c3 = n3;
        n0 = f0; n1 = f1; n2 = f2; n3 = f3;
    }
}

// Leaky update (reset from PREVIOUS membrane, subtract mechanism) + spike write.
__device__ __forceinline__ void leaky_write(const u64* acc2, float bias, float* m,
                                            float2* dst, int j) {
#pragma unroll
    for (int p = 0; p < P; p++) {
        float i0, i1;
        unpack2(acc2[p], i0, i1);
        float m0 = m[2*p], m1v = m[2*p+1];
        float r0 = (m0  > THR) ? THR : 0.f;
        float r1 = (m1v > THR) ? THR : 0.f;
        m0  = BETA * m0  + (i0 + bias) - r0;
        m1v = BETA * m1v + (i1 + bias) - r1;
        m[2*p] = m0; m[2*p+1] = m1v;
        dst[p*H + j] = make_float2(m0 > THR ? 1.f : 0.f, m1v > THR ? 1.f : 0.f);
    }
}

__global__ void prep_weights(const float* __restrict__ W1, const float* __restrict__ W2,
                             const float* __restrict__ W3, const float* __restrict__ W4,
                             const float* __restrict__ WO) {
    int idx = blockIdx.x * blockDim.x + threadIdx.x;
    if (idx < 5120) {
        int i = idx >> 8, jj = idx & 255;
        g_Wt[OFF_W1 + idx] = W1[jj*DIN + i];
    } else if (idx < 5120 + 65536) {
        int r = idx - 5120; int i = r >> 8, jj = r & 255;
        g_Wt[OFF_W2 + r] = W2[jj*H + i];
    } else if (idx < 5120 + 2*65536) {
        int r = idx - 5120 - 65536; int i = r >> 8, jj = r & 255;
        g_Wt[OFF_W3 + r] = W3[jj*H + i];
    } else if (idx < 5120 + 3*65536) {
        int r = idx - 5120 - 2*65536; int i = r >> 8, jj = r & 255;
        g_Wt[OFF_W4 + r] = W4[jj*H + i];
    } else if (idx < WT_TOTAL) {
        int r = idx - 5120 - 3*65536; int i = r >> 8, jj = r & 255;
        g_Wt[OFF_WO + r] = (jj < OUTN) ? WO[jj*H + i] : 0.f;
    }
}

__global__ void __launch_bounds__(256, 1)
snn_main(const float* __restrict__ x,
         const float* __restrict__ b1, const float* __restrict__ b2,
         const float* __restrict__ b3, const float* __restrict__ b4,
         float* __restrict__ out) {
    __shared__ float2 sb0[P * H];
    __shared__ float2 sb1[P * H];
    __shared__ float  mo_sh[BB][OUTN];

    const int j    = threadIdx.x;
    const int blk  = blockIdx.x;
    // blocks 0..123: 14 real rows; 124..147: 13 real rows + 1 dummy (row 0 dup)
    const int start = (blk < 124) ? blk * 14 : 13 * blk + 124;
    const int cnt   = (blk < 124) ? 14 : 13;
    const int wid = j >> 5, lane = j & 31;

    float m1[BB], m2[BB], m3[BB], m4[BB], mo[BB];
#pragma unroll
    for (int b = 0; b < BB; b++) { m1[b]=m2[b]=m3[b]=m4[b]=mo[b]=0.f; }
    const float bb1 = b1[j], bb2 = b2[j], bb3 = b3[j], bb4 = b4[j];

    float accA[P], accB[P];
#pragma unroll
    for (int k = 0; k < P; k++) { accA[k] = 0.f; accB[k] = 0.f; }

    const float* W1t = g_Wt + OFF_W1;
    const float* W2t = g_Wt + OFF_W2;
    const float* W3t = g_Wt + OFF_W3;
    const float* W4t = g_Wt + OFF_W4;
    const float* WOt = g_Wt + OFF_WO;

    u64 acc2[P];

    for (int t = 0; t < TSTEPS; t++) {
        // stage x_t into sb0 in packed-pair layout
        for (int idx = j; idx < BB * DIN; idx += 256) {
            int b = idx / DIN, i = idx - b * DIN;
            int rb = (b < cnt) ? b : 0;
            float v = x[(size_t)(start + rb) * (TSTEPS * DIN) + t * DIN + i];
            reinterpret_cast<float*>(sb0 + ((b >> 1) * H + i))[b & 1] = v;
        }
        __syncthreads();

        gemm_layer<DIN>(W1t, sb0, j, acc2);
        leaky_write(acc2, bb1, m1, sb1, j);
        __syncthreads();
        gemm_layer<H>(W2t, sb1, j, acc2);
        leaky_write(acc2, bb2, m2, sb0, j);
        __syncthreads();
        gemm_layer<H>(W3t, sb0, j, acc2);
        leaky_write(acc2, bb3, m3, sb1, j);
        __syncthreads();
        gemm_layer<H>(W4t, sb1, j, acc2);
        leaky_write(acc2, bb4, m4, sb0, j);
        __syncthreads();
        gemm_layer<H>(WOt, sb0, j, acc2);   // Wout cols >=200 are zero-padded

        if (j < OUTN) {
#pragma unroll
            for (int p = 0; p < P; p++) {
                float i0, i1;
                unpack2(acc2[p], i0, i1);
                float a = mo[2*p], bq = mo[2*p+1];
                float r0 = (a  > THR) ? THR : 0.f;
                float r1 = (bq > THR) ? THR : 0.f;
                a  = BETA * a  + i0 - r0;
                bq = BETA * bq + i1 - r1;
                mo[2*p] = a; mo[2*p+1] = bq;
                mo_sh[2*p][j] = a; mo_sh[2*p+1][j] = bq;
            }
        }
        __syncthreads();

        if (t > 50) {
            // warp `wid` handles row wid; warps 0..5 also handle row wid+8
            {
                const float* row = mo_sh[wid];
                float v[P]; float vmax = -3.0e38f;
#pragma unroll
                for (int k = 0; k < P; k++) {
                    int jj = lane + 32 * k;
                    v[k] = (jj < OUTN) ? row[jj] : -3.0e38f;
                    vmax = fmaxf(vmax, v[k]);
                }
#pragma unroll
                for (int o = 16; o; o >>= 1) vmax = fmaxf(vmax, __shfl_xor_sync(0xffffffffu, vmax, o));
                float e[P]; float s = 0.f;
#pragma unroll
                for (int k = 0; k < P; k++) {
                    int jj = lane + 32 * k;
                    e[k] = (jj < OUTN) ? __expf(v[k] - vmax) : 0.f;
                    s += e[k];
                }
#pragma unroll
                for (int o = 16; o; o >>= 1) s += __shfl_xor_sync(0xffffffffu, s, o);
                float inv = 1.0f / s;
#pragma unroll
                for (int k = 0; k < P; k++) accA[k] += e[k] * inv;
            }
            if (wid < 6) {
                const float* row = mo_sh[wid + 8];
                float v[P]; float vmax = -3.0e38f;
#pragma unroll
                for (int k = 0; k < P; k++) {
                    int jj = lane + 32 * k;
                    v[k] = (jj < OUTN) ? row[jj] : -3.0e38f;
                    vmax = fmaxf(vmax, v[k]);
                }
#pragma unroll
                for (int o = 16; o; o >>= 1) vmax = fmaxf(vmax, __shfl_xor_sync(0xffffffffu, vmax, o));
                float e[P]; float s = 0.f;
#pragma unroll
                for (int k = 0; k < P; k++) {
                    int jj = lane + 32 * k;
                    e[k] = (jj < OUTN) ? __expf(v[k] - vmax) : 0.f;
                    s += e[k];
                }
#pragma unroll
                for (int o = 16; o; o >>= 1) s += __shfl_xor_sync(0xffffffffu, s, o);
                float inv = 1.0f / s;
#pragma unroll
                for (int k = 0; k < P; k++) accB[k] += e[k] * inv;
            }
        }
        __syncthreads();
    }

    // write results: warp wid owns row wid (always real), and row wid+8 for wid<6
    {
        size_t g = (size_t)(start + wid) * OUTN;
#pragma unroll
        for (int k = 0; k < P; k++) {
            int jj = lane + 32 * k;
            if (jj < OUTN) out[g + jj] = accA[k];
        }
        if (wid < 6 && (wid + 8) < cnt) {
            size_t g2 = (size_t)(start + wid + 8) * OUTN;
#pragma unroll
            for (int k = 0; k < P; k++) {
                int jj = lane + 32 * k;
                if (jj < OUTN) out[g2 + jj] = accB[k];
            }
        }
    }
}

extern "C" void kernel_launch(void* const* d_in, const int* in_sizes, int n_in,
                              void* d_out, int out_size) {
    const float* x  = (const float*)d_in[0];
    const float* W1 = (const float*)d_in[1];
    const float* b1 = (const float*)d_in[2];
    const float* W2 = (const float*)d_in[3];
    const float* b2 = (const float*)d_in[4];
    const float* W3 = (const float*)d_in[5];
    const float* b3 = (const float*)d_in[6];
    const float* W4 = (const float*)d_in[7];
    const float* b4 = (const float*)d_in[8];
    const float* WO = (const float*)d_in[9];
    float* out = (float*)d_out;

    prep_weights<<<(WT_TOTAL + 255) / 256, 256>>>(W1, W2, W3, W4, WO);
    snn_main<<<148, 256>>>(x, b1, b2, b3, b4, out);
}